// round 1
// baseline (speedup 1.0000x reference)
#include <cuda_runtime.h>

#define BH 16
#define T 384
#define S 384
#define D 64
#define OUT_ELEMS (BH*T*D)   // 393216

// Scratch for transposed projections (e-major): [bh][e][t]
__device__ float4 g_qpT4[BH*D*T/4];
__device__ float4 g_kpT4[BH*D*S/4];

// ---------------------------------------------------------------------------
// Phase 1: qpT[bh][e][t] = sum_d X[bh][t][d] * W[e][d]   (both q and k)
// grid (16 bh, 6 t-chunks of 64, 2 which), 256 threads
// ---------------------------------------------------------------------------
__global__ __launch_bounds__(256) void proj_kernel(
    const float* __restrict__ query, const float* __restrict__ key,
    const float* __restrict__ Wq, const float* __restrict__ Wk)
{
    __shared__ float Xs[64][65];
    __shared__ float Ws[64][65];
    int bh = blockIdx.x, chunk = blockIdx.y, which = blockIdx.z;
    const float* X = which ? key : query;
    const float* W = which ? Wk : Wq;
    float* outT = which ? (float*)g_kpT4 : (float*)g_qpT4;
    int tid = threadIdx.x;

    for (int i = tid; i < 64*64; i += 256) {
        int r = i >> 6, c = i & 63;
        Xs[r][c] = X[((size_t)bh*T + (size_t)chunk*64 + r)*D + c];
        Ws[r][c] = W[i];
    }
    __syncthreads();

    int t  = tid & 63;        // within warp: consecutive t -> conflict-free Xs
    int e0 = (tid >> 6) * 16; // same across warp -> Ws broadcast
    float acc[16];
    #pragma unroll
    for (int k = 0; k < 16; k++) acc[k] = 0.f;

    #pragma unroll 4
    for (int d = 0; d < 64; d++) {
        float xv = Xs[t][d];
        #pragma unroll
        for (int k = 0; k < 16; k++)
            acc[k] = fmaf(xv, Ws[e0+k][d], acc[k]);
    }
    #pragma unroll
    for (int k = 0; k < 16; k++)
        outT[((size_t)bh*D + e0 + k)*T + (size_t)chunk*64 + t] = acc[k];
}

// ---------------------------------------------------------------------------
// Phase 2: fused score(tanh) + softmax + attn@value
// grid (24 t-chunks, 16 bh), 256 threads. One CTA: 16 t-rows x full s=384.
// Per-thread register tile: 4 t x 6 s. kp streamed in 4 chunks of 16 e.
// ---------------------------------------------------------------------------
__global__ __launch_bounds__(256) void attn_kernel(
    const float* __restrict__ value, const float* __restrict__ v_w,
    float* __restrict__ out, float* __restrict__ attn)
{
    __shared__ __align__(16) float sh_kp[16*384]; // kp chunk; later aliased as scores[16][384]
    __shared__ float sh_qp[64][16];
    __shared__ float sh_vw[64];

    int bh  = blockIdx.y;
    int t0  = blockIdx.x * 16;
    int tid = threadIdx.x;

    // qp tile (64 e x 16 t) + v_w
    const float* qbase = (const float*)g_qpT4 + (size_t)bh*D*T;
    for (int i = tid; i < 64*16; i += 256) {
        int e = i >> 4, tl = i & 15;
        sh_qp[e][tl] = qbase[(size_t)e*T + t0 + tl];
    }
    if (tid < 64) sh_vw[tid] = v_w[tid];

    int sx = tid & 63;   // s lane (warp-consecutive -> conflict-free kp LDS)
    int ty = tid >> 6;   // t group (same across warp -> qp broadcast)

    float acc[4][6];
    #pragma unroll
    for (int k = 0; k < 4; k++)
        #pragma unroll
        for (int j = 0; j < 6; j++) acc[k][j] = 0.f;

    const float4* kbase4 = g_kpT4 + (size_t)bh*D*S/4;

    for (int c = 0; c < 4; c++) {
        __syncthreads();
        // load kp chunk: 16 e-rows x 384 s (24 KB), coalesced float4
        const float4* src = kbase4 + (size_t)c*16*S/4;
        float4* dst = (float4*)sh_kp;
        #pragma unroll
        for (int i = tid; i < 16*384/4; i += 256) dst[i] = src[i];
        __syncthreads();

        #pragma unroll
        for (int ec = 0; ec < 16; ec++) {
            int e = c*16 + ec;
            float vw = sh_vw[e];
            float qv[4], kv[6];
            #pragma unroll
            for (int k = 0; k < 4; k++) qv[k] = sh_qp[e][ty*4+k];
            #pragma unroll
            for (int j = 0; j < 6; j++) kv[j] = sh_kp[ec*384 + sx + 64*j];
            #pragma unroll
            for (int k = 0; k < 4; k++)
                #pragma unroll
                for (int j = 0; j < 6; j++) {
                    float x = qv[k] + kv[j];
                    float th;
                    asm("tanh.approx.f32 %0, %1;" : "=f"(th) : "f"(x));
                    acc[k][j] = fmaf(vw, th, acc[k][j]);
                }
        }
    }
    __syncthreads();

    // dump scores into the (now free) kp buffer
    float (*scores)[384] = (float(*)[384])sh_kp;
    #pragma unroll
    for (int k = 0; k < 4; k++)
        #pragma unroll
        for (int j = 0; j < 6; j++)
            scores[ty*4+k][sx + 64*j] = acc[k][j];
    __syncthreads();

    // softmax: 8 warps, 2 rows each; write attn to global, keep normalized in smem
    int w = tid >> 5, lane = tid & 31;
    for (int r = w; r < 16; r += 8) {
        float vals[12];
        float m = -1e30f;
        #pragma unroll
        for (int i = 0; i < 12; i++) {
            vals[i] = scores[r][lane + 32*i];
            m = fmaxf(m, vals[i]);
        }
        #pragma unroll
        for (int off = 16; off; off >>= 1)
            m = fmaxf(m, __shfl_xor_sync(0xffffffffu, m, off));
        float sum = 0.f;
        #pragma unroll
        for (int i = 0; i < 12; i++) {
            float p;
            float xe = (vals[i] - m) * 1.4426950408889634f;
            asm("ex2.approx.f32 %0, %1;" : "=f"(p) : "f"(xe));
            vals[i] = p;
            sum += p;
        }
        #pragma unroll
        for (int off = 16; off; off >>= 1)
            sum += __shfl_xor_sync(0xffffffffu, sum, off);
        float inv = 1.0f / sum;
        size_t arow = ((size_t)bh*T + t0 + r) * S;
        #pragma unroll
        for (int i = 0; i < 12; i++) {
            float p = vals[i] * inv;
            scores[r][lane + 32*i] = p;
            attn[arow + lane + 32*i] = p;
        }
    }
    __syncthreads();

    // epilogue: out[t0+tl][d] = sum_s attn[tl][s] * value[s][d]
    int dx = sx; // 0..63, warp-coalesced value loads
    float acc2[4] = {0.f, 0.f, 0.f, 0.f};
    const float* vp = value + (size_t)bh*S*D + dx;
    #pragma unroll 2
    for (int s = 0; s < 384; s += 4) {
        float v0 = __ldg(vp + (size_t)(s+0)*D);
        float v1 = __ldg(vp + (size_t)(s+1)*D);
        float v2 = __ldg(vp + (size_t)(s+2)*D);
        float v3 = __ldg(vp + (size_t)(s+3)*D);
        #pragma unroll
        for (int k = 0; k < 4; k++) {
            float4 a = *(const float4*)&scores[ty*4+k][s];
            acc2[k] = fmaf(a.x, v0, fmaf(a.y, v1, fmaf(a.z, v2, fmaf(a.w, v3, acc2[k]))));
        }
    }
    #pragma unroll
    for (int k = 0; k < 4; k++)
        out[((size_t)bh*T + t0 + ty*4 + k)*D + dx] = acc2[k];
}

// ---------------------------------------------------------------------------
extern "C" void kernel_launch(void* const* d_in, const int* in_sizes, int n_in,
                              void* d_out, int out_size)
{
    (void)in_sizes; (void)n_in; (void)out_size;
    const float* query = (const float*)d_in[0];
    const float* key   = (const float*)d_in[1];
    const float* value = (const float*)d_in[2];
    const float* Wq    = (const float*)d_in[3];
    const float* Wk    = (const float*)d_in[4];
    const float* vw    = (const float*)d_in[5];
    float* out  = (float*)d_out;
    float* attn = out + OUT_ELEMS;

    proj_kernel<<<dim3(16, 6, 2), 256>>>(query, key, Wq, Wk);
    attn_kernel<<<dim3(24, 16), 256>>>(value, vw, out, attn);
}